// round 6
// baseline (speedup 1.0000x reference)
#include <cuda_runtime.h>
#include <math.h>

// ---------------- problem constants ----------------
#define NB   64
#define NCQ  5
#define LQ   20
#define NF   20
#define CIN  8192
#define EMB  300
#define EMBP 304
#define HID  512
#define G4   2048
#define RT   320
#define NVOC 8000

// ---------------- device scratch ----------------
__device__ float g_embp[(size_t)NVOC * EMBP];        // raw fp32, zero-padded
__device__ float g_Wt1p[(size_t)G4 * EMBP];          // raw fp32, original gate layout, padded
// recurrent weights: reordered (n=j*4+q) split into hi/lo tf32 parts
__device__ float g_Whv1h[(size_t)G4 * HID], g_Whv1l[(size_t)G4 * HID];
__device__ float g_Wiv2h[(size_t)G4 * HID], g_Wiv2l[(size_t)G4 * HID];
__device__ float g_Whv2h[(size_t)G4 * HID], g_Whv2l[(size_t)G4 * HID];
__device__ float g_Wht1h[(size_t)G4 * HID], g_Wht1l[(size_t)G4 * HID];
__device__ float g_Wit2h[(size_t)G4 * HID], g_Wit2l[(size_t)G4 * HID];
__device__ float g_Wht2h[(size_t)G4 * HID], g_Wht2l[(size_t)G4 * HID];
__device__ float g_bv1re[G4];
__device__ float g_bt1re[G4];
__device__ float g_bv2re[G4];
__device__ float g_bt2re[G4];

__device__ float g_Xv[(size_t)NF * NB * G4];         // [t][b][n], n=j*4+q
__device__ float g_Xt[(size_t)LQ * RT * G4];
__device__ float g_vh[2][2][NB * HID];
__device__ float g_vc[2][2][NB * HID];
__device__ float g_vcand[NB * HID];
__device__ float g_th[2][2][RT * HID];
__device__ float g_tc[2][2][RT * HID];
__device__ float g_tcand[RT * HID];
__device__ float g_vec[2 * HID];
__device__ float g_cnst;
__device__ unsigned g_cnt = 0;
__device__ unsigned g_gen = 0;

// ---------------- helpers ----------------
__device__ __forceinline__ float tf32r(float x) {
    unsigned u;
    asm("cvt.rna.tf32.f32 %0, %1;" : "=r"(u) : "f"(x));
    return __uint_as_float(u);
}
__device__ __forceinline__ unsigned fbits(float x) { return __float_as_uint(x); }

__device__ __forceinline__ void mma8(float* c, unsigned a0, unsigned a1,
                                     unsigned a2, unsigned a3,
                                     unsigned b0, unsigned b1) {
    asm volatile(
        "mma.sync.aligned.m16n8k8.row.col.f32.tf32.tf32.f32 "
        "{%0,%1,%2,%3}, {%4,%5,%6,%7}, {%8,%9}, {%0,%1,%2,%3};"
        : "+f"(c[0]), "+f"(c[1]), "+f"(c[2]), "+f"(c[3])
        : "r"(a0), "r"(a1), "r"(a2), "r"(a3), "r"(b0), "r"(b1));
}

__device__ __forceinline__ float sigf(float x) {
    return 1.0f / (1.0f + __expf(-x));
}

// split a float4 into tf32 hi/lo parts, store to smem
__device__ __forceinline__ void split4(float4 v, float* dh, float* dl) {
    float h0 = tf32r(v.x), h1 = tf32r(v.y), h2 = tf32r(v.z), h3 = tf32r(v.w);
    dh[0] = h0; dh[1] = h1; dh[2] = h2; dh[3] = h3;
    dl[0] = tf32r(v.x - h0); dl[1] = tf32r(v.y - h1);
    dl[2] = tf32r(v.z - h2); dl[3] = tf32r(v.w - h3);
}

// grid barrier: generation counter (graph-replay safe), light backoff spin
__device__ __forceinline__ void grid_sync(unsigned nb) {
    __syncthreads();
    if (threadIdx.x == 0) {
        unsigned gen = *(volatile unsigned*)&g_gen;
        __threadfence();
        if (atomicAdd(&g_cnt, 1u) == nb - 1u) {
            g_cnt = 0;
            __threadfence();
            atomicAdd(&g_gen, 1u);
        } else {
            while (*(volatile unsigned*)&g_gen == gen) { __nanosleep(16); }
        }
        __threadfence();
    }
    __syncthreads();
}

// ==================================================================
// prep: ALL conversion work in one launch.
//  region 0: embed pad (raw)
//  region 1: Wih_t1 pad (raw, original layout)
//  region 2: 6 recurrent weights -> reorder + tf32 hi/lo split
//  region 3: bias reorder
// ==================================================================
__global__ void __launch_bounds__(256) prep_main(
    const float* __restrict__ embed, const float* __restrict__ Wt1,
    const float* __restrict__ Whv1, const float* __restrict__ Wiv2,
    const float* __restrict__ Whv2, const float* __restrict__ Wht1,
    const float* __restrict__ Wit2, const float* __restrict__ Wht2,
    const float* __restrict__ bv1, const float* __restrict__ bt1,
    const float* __restrict__ bv2, const float* __restrict__ bt2)
{
    const int E0 = NVOC * EMBP;            // 2,432,000
    const int E1 = E0 + G4 * EMBP;         // + 622,592
    const int WSZ = G4 * HID;              // 1,048,576
    const int E2 = E1 + 6 * WSZ;
    const int E3 = E2 + G4;
    for (int i = blockIdx.x * blockDim.x + threadIdx.x; i < E3;
         i += gridDim.x * blockDim.x) {
        if (i < E0) {
            int r = i / EMBP, k = i - r * EMBP;
            g_embp[i] = (k < EMB) ? embed[r * EMB + k] : 0.0f;
        } else if (i < E1) {
            int ii = i - E0;
            int r = ii / EMBP, k = ii - r * EMBP;
            g_Wt1p[ii] = (k < EMB) ? Wt1[r * EMB + k] : 0.0f;
        } else if (i < E2) {
            int ii = i - E1;
            int widx = ii / WSZ;
            int idx = ii - widx * WSZ;
            int nn = idx >> 9, k = idx & 511;
            int j = nn >> 2, q = nn & 3;
            const float* src;
            float *dh, *dl;
            switch (widx) {
                case 0: src = Whv1; dh = g_Whv1h; dl = g_Whv1l; break;
                case 1: src = Wiv2; dh = g_Wiv2h; dl = g_Wiv2l; break;
                case 2: src = Whv2; dh = g_Whv2h; dl = g_Whv2l; break;
                case 3: src = Wht1; dh = g_Wht1h; dl = g_Wht1l; break;
                case 4: src = Wit2; dh = g_Wit2h; dl = g_Wit2l; break;
                default: src = Wht2; dh = g_Wht2h; dl = g_Wht2l; break;
            }
            float v = src[(size_t)(q * HID + j) * HID + k];
            float h = tf32r(v);
            dh[idx] = h;
            dl[idx] = tf32r(v - h);
        } else {
            int nn = i - E2;
            int j = nn >> 2, q = nn & 3;
            int gidx = q * HID + j;
            g_bv1re[nn] = bv1[gidx];
            g_bt1re[nn] = bt1[gidx];
            g_bv2re[nn] = bv2[gidx];
            g_bt2re[nn] = bt2[gidx];
        }
    }
}

// ==================================================================
// Input GEMM, split-tf32: C[r][n] = biasre[n] + sum_k A(r)[k]*W[n][k]
// A raw fp32, W raw fp32 in ORIGINAL gate layout (row = q*512+j).
// BM=BN=128, BK=16, 256 thr, warps 4x2, warp tile 32x64.
// Register-prefetched k-loop; hi/lo split at smem store.
// ==================================================================
__global__ void __launch_bounds__(256) in_gemm_split(
    const float* __restrict__ Abase, const int* __restrict__ qidx,
    const float* __restrict__ Wraw, const float* __restrict__ biasre,
    float* __restrict__ C, int K, int mode, int ntn)
{
    __shared__ float Ah[128][20], Al[128][20];
    __shared__ float Bh[128][20], Bl[128][20];

    int tm = blockIdx.x / ntn, tn = blockIdx.x % ntn;
    int m0 = tm * 128, n0 = tn * 128;
    int tid = threadIdx.x;
    int w = tid >> 5, lane = tid & 31;
    int rg = w >> 1, cg = w & 1;
    int g = lane >> 2, tg = lane & 3;
    int cq = (tid & 3) * 4;

    const float* aptr[2];
    const float* wptr[2];
    #pragma unroll
    for (int s = 0; s < 2; s++) {
        int rloc = (tid >> 2) + s * 64;
        int r = m0 + rloc;
        if (mode == 0) {
            int t = r >> 6, b = r & 63;
            aptr[s] = Abase + (size_t)(b * NF + t) * K;
        } else {
            int rr = r % RT, t = r / RT;
            int qid = qidx[rr * LQ + t];
            aptr[s] = Abase + (size_t)qid * K;
        }
        int n = n0 + rloc;
        int srow = (n & 3) * HID + (n >> 2);
        wptr[s] = Wraw + (size_t)srow * K;
    }

    float acc[2][8][4];
    #pragma unroll
    for (int mi = 0; mi < 2; mi++)
        #pragma unroll
        for (int nc = 0; nc < 8; nc++)
            #pragma unroll
            for (int v = 0; v < 4; v++) acc[mi][nc][v] = 0.0f;

    int niter = K / 16;
    float4 ra[2], rw[2];
    #pragma unroll
    for (int s = 0; s < 2; s++) {
        ra[s] = *(const float4*)(aptr[s] + cq);
        rw[s] = *(const float4*)(wptr[s] + cq);
    }

    for (int it = 0; it < niter; it++) {
        #pragma unroll
        for (int s = 0; s < 2; s++) {
            int rloc = (tid >> 2) + s * 64;
            split4(ra[s], &Ah[rloc][cq], &Al[rloc][cq]);
            split4(rw[s], &Bh[rloc][cq], &Bl[rloc][cq]);
        }
        __syncthreads();
        if (it + 1 < niter) {
            int kb = (it + 1) * 16;
            #pragma unroll
            for (int s = 0; s < 2; s++) {
                ra[s] = *(const float4*)(aptr[s] + kb + cq);
                rw[s] = *(const float4*)(wptr[s] + kb + cq);
            }
        }
        #pragma unroll
        for (int ks = 0; ks < 2; ks++) {
            unsigned ah[2][4], al[2][4];
            #pragma unroll
            for (int mi = 0; mi < 2; mi++) {
                int ar = rg * 32 + mi * 16;
                ah[mi][0] = fbits(Ah[ar + g][ks * 8 + tg]);
                ah[mi][1] = fbits(Ah[ar + g + 8][ks * 8 + tg]);
                ah[mi][2] = fbits(Ah[ar + g][ks * 8 + tg + 4]);
                ah[mi][3] = fbits(Ah[ar + g + 8][ks * 8 + tg + 4]);
                al[mi][0] = fbits(Al[ar + g][ks * 8 + tg]);
                al[mi][1] = fbits(Al[ar + g + 8][ks * 8 + tg]);
                al[mi][2] = fbits(Al[ar + g][ks * 8 + tg + 4]);
                al[mi][3] = fbits(Al[ar + g + 8][ks * 8 + tg + 4]);
            }
            #pragma unroll
            for (int nc = 0; nc < 8; nc++) {
                int nr = cg * 64 + nc * 8 + g;
                unsigned bh0 = fbits(Bh[nr][ks * 8 + tg]);
                unsigned bh1 = fbits(Bh[nr][ks * 8 + tg + 4]);
                unsigned bl0 = fbits(Bl[nr][ks * 8 + tg]);
                unsigned bl1 = fbits(Bl[nr][ks * 8 + tg + 4]);
                #pragma unroll
                for (int mi = 0; mi < 2; mi++) {
                    mma8(acc[mi][nc], ah[mi][0], ah[mi][1], ah[mi][2], ah[mi][3], bh0, bh1);
                    mma8(acc[mi][nc], ah[mi][0], ah[mi][1], ah[mi][2], ah[mi][3], bl0, bl1);
                    mma8(acc[mi][nc], al[mi][0], al[mi][1], al[mi][2], al[mi][3], bh0, bh1);
                }
            }
        }
        __syncthreads();
    }

    #pragma unroll
    for (int nc = 0; nc < 8; nc++) {
        int col = n0 + cg * 64 + nc * 8 + 2 * tg;
        float2 bb = *(const float2*)(biasre + col);
        #pragma unroll
        for (int mi = 0; mi < 2; mi++) {
            int row0 = m0 + rg * 32 + mi * 16 + g;
            *(float2*)(C + (size_t)row0 * G4 + col) =
                make_float2(acc[mi][nc][0] + bb.x, acc[mi][nc][1] + bb.y);
            *(float2*)(C + (size_t)(row0 + 8) * G4 + col) =
                make_float2(acc[mi][nc][2] + bb.x, acc[mi][nc][3] + bb.y);
        }
    }
}

// ==================================================================
// Fused LSTM stage, split-tf32. Block tile 16*RG rows x 32 j.
// ==================================================================
template <int RG>
__device__ __forceinline__ void stage_mma(
    float* sAh, float* sAl, float* sBh, float* sBl,
    const float* __restrict__ A1,
    const float* __restrict__ W1h, const float* __restrict__ W1l,
    const float* __restrict__ A2,
    const float* __restrict__ W2h, const float* __restrict__ W2l,
    const float* __restrict__ Xadd, const float* __restrict__ biasre,
    const float* __restrict__ hOld, const float* __restrict__ cOld,
    float* __restrict__ hNew, float* __restrict__ cNew,
    float* __restrict__ hCand,
    const int* __restrict__ qlen, int t, int m0, int j0)
{
    const int NT = 64 * RG;
    int tid = threadIdx.x;
    int w = tid >> 5, lane = tid & 31;
    int rg = w >> 1, jg = w & 1;
    int g = lane >> 2, tg = lane & 3;

    float acc[8][4];
    #pragma unroll
    for (int ch = 0; ch < 8; ch++)
        #pragma unroll
        for (int v = 0; v < 4; v++) acc[ch][v] = 0.0f;

    int iters = A2 ? 64 : 32;
    for (int it = 0; it < iters; it++) {
        int kb = it * 16;
        const float* Asrc;
        const float* Wsh; const float* Wsl; int ko;
        if (kb < HID) { Asrc = A1; Wsh = W1h; Wsl = W1l; ko = kb; }
        else          { Asrc = A2; Wsh = W2h; Wsl = W2l; ko = kb - HID; }

        {   // A fill: state fp32 -> hi/lo split
            int rloc = tid >> 2, acq = (tid & 3) * 4;
            float4 v = __ldcg((const float4*)(Asrc + (size_t)(m0 + rloc) * HID + ko + acq));
            split4(v, sAh + rloc * 20 + acq, sAl + rloc * 20 + acq);
        }
        // B fill: precomputed hi/lo weights (reordered layout)
        for (int s = tid; s < 512; s += NT) {
            int nloc = s >> 2, bcq = (s & 3) * 4;
            size_t off = (size_t)(j0 * 4 + nloc) * HID + ko + bcq;
            float4 vh = *(const float4*)(Wsh + off);
            float4 vl = *(const float4*)(Wsl + off);
            float* dh = sBh + nloc * 17 + bcq;
            float* dl = sBl + nloc * 17 + bcq;
            dh[0] = vh.x; dh[1] = vh.y; dh[2] = vh.z; dh[3] = vh.w;
            dl[0] = vl.x; dl[1] = vl.y; dl[2] = vl.z; dl[3] = vl.w;
        }
        __syncthreads();
        #pragma unroll
        for (int ks = 0; ks < 2; ks++) {
            int ar = rg * 16;
            unsigned ah0 = fbits(sAh[(ar + g) * 20 + ks * 8 + tg]);
            unsigned ah1 = fbits(sAh[(ar + g + 8) * 20 + ks * 8 + tg]);
            unsigned ah2 = fbits(sAh[(ar + g) * 20 + ks * 8 + tg + 4]);
            unsigned ah3 = fbits(sAh[(ar + g + 8) * 20 + ks * 8 + tg + 4]);
            unsigned al0 = fbits(sAl[(ar + g) * 20 + ks * 8 + tg]);
            unsigned al1 = fbits(sAl[(ar + g + 8) * 20 + ks * 8 + tg]);
            unsigned al2 = fbits(sAl[(ar + g) * 20 + ks * 8 + tg + 4]);
            unsigned al3 = fbits(sAl[(ar + g + 8) * 20 + ks * 8 + tg + 4]);
            #pragma unroll
            for (int ch = 0; ch < 8; ch++) {
                int q = ch >> 1, jh = ch & 1;
                int n = (jg * 16 + jh * 8 + g) * 4 + q;
                unsigned bh0 = fbits(sBh[n * 17 + ks * 8 + tg]);
                unsigned bh1 = fbits(sBh[n * 17 + ks * 8 + tg + 4]);
                unsigned bl0 = fbits(sBl[n * 17 + ks * 8 + tg]);
                unsigned bl1 = fbits(sBl[n * 17 + ks * 8 + tg + 4]);
                mma8(acc[ch], ah0, ah1, ah2, ah3, bh0, bh1);
                mma8(acc[ch], ah0, ah1, ah2, ah3, bl0, bl1);
                mma8(acc[ch], al0, al1, al2, al3, bh0, bh1);
            }
        }
        __syncthreads();
    }

    // fused LSTM cell epilogue
    #pragma unroll
    for (int rs = 0; rs < 2; rs++) {
        int r = m0 + rg * 16 + g + rs * 8;
        bool up = qlen ? (t < __ldg(&qlen[r / NCQ])) : true;
        #pragma unroll
        for (int jh = 0; jh < 2; jh++) {
            int jb = j0 + jg * 16 + jh * 8 + 2 * tg;
            float2 co = __ldcg((const float2*)(cOld + (size_t)r * HID + jb));
            float2 ho = __ldcg((const float2*)(hOld + (size_t)r * HID + jb));
            float rh[2], rc[2], rcd[2];
            #pragma unroll
            for (int cp = 0; cp < 2; cp++) {
                int j = jb + cp;
                float iv = acc[0 + jh][rs * 2 + cp];
                float fv = acc[2 + jh][rs * 2 + cp];
                float gv = acc[4 + jh][rs * 2 + cp];
                float ov = acc[6 + jh][rs * 2 + cp];
                if (Xadd) {
                    float4 x = *(const float4*)(Xadd + (size_t)r * G4 + j * 4);
                    iv += x.x; fv += x.y; gv += x.z; ov += x.w;
                }
                if (biasre) {
                    float4 bx = *(const float4*)(biasre + j * 4);
                    iv += bx.x; fv += bx.y; gv += bx.z; ov += bx.w;
                }
                float cold = cp ? co.y : co.x;
                float ig = sigf(iv), fg = sigf(fv);
                float gt = tanhf(gv), og = sigf(ov);
                float cn = fg * cold + ig * gt;
                float hc = og * tanhf(cn);
                rcd[cp] = hc;
                rh[cp] = up ? hc : (cp ? ho.y : ho.x);
                rc[cp] = up ? cn : cold;
            }
            if (hCand)
                *(float2*)(hCand + (size_t)r * HID + jb) = make_float2(rcd[0], rcd[1]);
            *(float2*)(hNew + (size_t)r * HID + jb) = make_float2(rh[0], rh[1]);
            *(float2*)(cNew + (size_t)r * HID + jb) = make_float2(rc[0], rc[1]);
        }
    }
}

// ---------------- persistent video recurrence: 32 blocks x 128 thr ----------------
__global__ void __launch_bounds__(128) vrec_kernel()
{
    __shared__ float sAh[32 * 20], sAl[32 * 20];
    __shared__ float sBh[128 * 17], sBl[128 * 17];
    unsigned nb = gridDim.x;
    int m0 = (blockIdx.x >> 4) * 32;
    int j0 = (blockIdx.x & 15) * 32;

    for (int i = blockIdx.x * blockDim.x + threadIdx.x; i < NB * HID;
         i += gridDim.x * blockDim.x) {
        g_vh[0][0][i] = 0.0f; g_vc[0][0][i] = 0.0f;
        g_vh[1][0][i] = 0.0f; g_vc[1][0][i] = 0.0f;
    }
    grid_sync(nb);

    for (int t = 0; t < NF; t++) {
        int p = t & 1;
        stage_mma<2>(sAh, sAl, sBh, sBl,
                     g_vh[0][p], g_Whv1h, g_Whv1l, nullptr, nullptr, nullptr,
                     g_Xv + (size_t)t * NB * G4, nullptr,
                     g_vh[0][p], g_vc[0][p],
                     g_vh[0][1 - p], g_vc[0][1 - p], g_vcand,
                     nullptr, 0, m0, j0);
        grid_sync(nb);
        stage_mma<2>(sAh, sAl, sBh, sBl,
                     g_vcand, g_Wiv2h, g_Wiv2l, g_vh[1][p], g_Whv2h, g_Whv2l,
                     nullptr, g_bv2re,
                     g_vh[1][p], g_vc[1][p],
                     g_vh[1][1 - p], g_vc[1][1 - p], nullptr,
                     nullptr, 0, m0, j0);
        grid_sync(nb);
    }
}

// ---------------- persistent text recurrence: 80 blocks x 256 thr ----------------
__global__ void __launch_bounds__(256) trec_kernel(const int* __restrict__ qlen)
{
    __shared__ float sAh[64 * 20], sAl[64 * 20];
    __shared__ float sBh[128 * 17], sBl[128 * 17];
    unsigned nb = gridDim.x;
    int m0 = (blockIdx.x >> 4) * 64;
    int j0 = (blockIdx.x & 15) * 32;

    for (int i = blockIdx.x * blockDim.x + threadIdx.x; i < RT * HID;
         i += gridDim.x * blockDim.x) {
        int r = i >> 9;
        int j = i & (HID - 1);
        int src = (r / NCQ) * HID + j;
        g_th[0][0][i] = g_vh[0][0][src];
        g_tc[0][0][i] = g_vc[0][0][src];
        g_th[1][0][i] = g_vh[1][0][src];
        g_tc[1][0][i] = g_vc[1][0][src];
    }
    grid_sync(nb);

    for (int t = 0; t < LQ; t++) {
        int p = t & 1;
        stage_mma<4>(sAh, sAl, sBh, sBl,
                     g_th[0][p], g_Wht1h, g_Wht1l, nullptr, nullptr, nullptr,
                     g_Xt + (size_t)t * RT * G4, nullptr,
                     g_th[0][p], g_tc[0][p],
                     g_th[0][1 - p], g_tc[0][1 - p], g_tcand,
                     qlen, t, m0, j0);
        grid_sync(nb);
        stage_mma<4>(sAh, sAl, sBh, sBl,
                     g_tcand, g_Wit2h, g_Wit2l, g_th[1][p], g_Wht2h, g_Wht2l,
                     nullptr, g_bt2re,
                     g_th[1][p], g_tc[1][p],
                     g_th[1][1 - p], g_tc[1][1 - p], nullptr,
                     qlen, t, m0, j0);
        grid_sync(nb);
    }
}

// ---------------- decoder collapse ----------------
__global__ void __launch_bounds__(1024) dec_vec_kernel(
    const float* __restrict__ d1w, const float* __restrict__ d1b,
    const float* __restrict__ d2w, const float* __restrict__ d2b)
{
    __shared__ float red[1024];
    int k = threadIdx.x;
    float s = 0.0f;
    for (int m = 0; m < 1024; m++) s += d2w[m] * d1w[m * 1024 + k];
    g_vec[k] = s;
    red[k] = d2w[k] * d1b[k];
    __syncthreads();
    for (int off = 512; off > 0; off >>= 1) {
        if (k < off) red[k] += red[k + off];
        __syncthreads();
    }
    if (k == 0) g_cnst = red[0] + d2b[0];
}

// ---------------- outputs + argmax ----------------
__global__ void __launch_bounds__(256) dec_out_kernel(float* __restrict__ out,
                                                      int out_size)
{
    int b = blockIdx.x;
    int tid = threadIdx.x;
    __shared__ float red[256];
    __shared__ float vals[NCQ];

    for (int nc = 0; nc < NCQ; nc++) {
        int r = b * NCQ + nc;
        float s = 0.0f;
        for (int k = tid; k < 2 * HID; k += 256) {
            float sv = (k < HID) ? g_th[0][0][r * HID + k]
                                 : g_th[1][0][r * HID + (k - HID)];
            s += sv * g_vec[k];
        }
        red[tid] = s;
        __syncthreads();
        for (int off = 128; off > 0; off >>= 1) {
            if (tid < off) red[tid] += red[tid + off];
            __syncthreads();
        }
        if (tid == 0) vals[nc] = red[0] + g_cnst;
        __syncthreads();
    }

    if (tid == 0) {
        float best = vals[0];
        int bi = 0;
        #pragma unroll
        for (int nc = 0; nc < NCQ; nc++) {
            out[b * NCQ + nc] = vals[nc];
            if (vals[nc] > best) { best = vals[nc]; bi = nc; }
        }
        if (out_size >= RT + NB) out[RT + b] = (float)bi;
    }
}

// ==================================================================
extern "C" void kernel_launch(void* const* d_in, const int* in_sizes, int n_in,
                              void* d_out, int out_size)
{
    const float* video  = (const float*)d_in[0];
    const int*   quest  = (const int*)  d_in[1];
    const int*   qlen   = (const int*)  d_in[2];
    const float* embed  = (const float*)d_in[3];
    const float* Wih_t1 = (const float*)d_in[4];
    const float* Whh_t1 = (const float*)d_in[5];
    const float* b_t1   = (const float*)d_in[6];
    const float* Wih_t2 = (const float*)d_in[7];
    const float* Whh_t2 = (const float*)d_in[8];
    const float* b_t2   = (const float*)d_in[9];
    const float* Wih_v1 = (const float*)d_in[10];
    const float* Whh_v1 = (const float*)d_in[11];
    const float* b_v1   = (const float*)d_in[12];
    const float* Wih_v2 = (const float*)d_in[13];
    const float* Whh_v2 = (const float*)d_in[14];
    const float* b_v2   = (const float*)d_in[15];
    const float* d1w    = (const float*)d_in[16];
    const float* d1b    = (const float*)d_in[17];
    const float* d2w    = (const float*)d_in[18];
    const float* d2b    = (const float*)d_in[19];
    float* out = (float*)d_out;

    float* pembp; cudaGetSymbolAddress((void**)&pembp, g_embp);
    float* pWt1p; cudaGetSymbolAddress((void**)&pWt1p, g_Wt1p);
    float* pbv1;  cudaGetSymbolAddress((void**)&pbv1,  g_bv1re);
    float* pbt1;  cudaGetSymbolAddress((void**)&pbt1,  g_bt1re);
    float* pXv;   cudaGetSymbolAddress((void**)&pXv,   g_Xv);
    float* pXt;   cudaGetSymbolAddress((void**)&pXt,   g_Xt);

    // launch 0: all prep in one kernel
    prep_main<<<2048, 256>>>(embed, Wih_t1,
                             Whh_v1, Wih_v2, Whh_v2, Whh_t1, Wih_t2, Whh_t2,
                             b_v1, b_t1, b_v2, b_t2);
    // launch 1: decoder collapse
    dec_vec_kernel<<<1, 1024>>>(d1w, d1b, d2w, d2b);
    // launch 2: video input GEMM (raw inputs, on-the-fly split)
    in_gemm_split<<<10 * 16, 256>>>(video, nullptr, Wih_v1, pbv1, pXv, CIN, 0, 16);
    // launch 3: text input GEMM (padded buffers)
    in_gemm_split<<<50 * 16, 256>>>(pembp, quest, pWt1p, pbt1, pXt, EMBP, 1, 16);
    // launch 4: video recurrence
    vrec_kernel<<<32, 128>>>();
    // launch 5: text recurrence (ncu -s 5 captures this one)
    trec_kernel<<<80, 256>>>(qlen);
    // launch 6: outputs + argmax
    dec_out_kernel<<<NB, 256>>>(out, out_size);
}